// round 1
// baseline (speedup 1.0000x reference)
#include <cuda_runtime.h>

#define N_NODES 100000
#define E_EDGES 1600000

// ---------------- scratch (device globals; no allocations allowed) ----------
__device__ int   g_is64;                 // 1 if edge_index is int64, 0 if int32
__device__ int   g_row[E_EDGES];
__device__ int   g_col[E_EDGES];
__device__ float g_deg[N_NODES];         // in-degree (edges only; +1 self loop at use)
__device__ float g_dinv[N_NODES];
__device__ float g_t[N_NODES * 2];       // layer-1 aggregation of dinv[r]*x[r]
__device__ float g_s2[N_NODES * 32];     // dinv[v] * (h1[v] @ W2)
__device__ float g_agg2[N_NODES * 32];   // layer-2 aggregation
__device__ float g_a[N_NODES * 16];      // h2[v] @ Wm1[0:32]
__device__ float g_c[N_NODES * 16];      // h2[v] @ Wm1[32:64]

// ---------------- kernels ----------------------------------------------------

// Zero all accumulators (device globals persist across graph replays).
__global__ void k_zero() {
    int i = blockIdx.x * blockDim.x + threadIdx.x;
    if (i < N_NODES * 32) g_agg2[i] = 0.0f;
    if (i < N_NODES * 2)  g_t[i]    = 0.0f;
    if (i < N_NODES)      g_deg[i]  = 0.0f;
}

// Detect int64 vs int32 edge_index: if stored as int64 (values < 2^17), every
// odd 32-bit word of the first 1024 entries is zero. Real int32 data has
// random values in [0,100000) there -> virtually impossible all zero.
__global__ void k_detect(const int* ei32) {
    __shared__ int s_any;
    if (threadIdx.x == 0) s_any = 0;
    __syncthreads();
    int v = 0;
    for (int i = threadIdx.x; i < 1024; i += blockDim.x)
        v |= ei32[2 * i + 1];
    if (v) atomicOr(&s_any, 1);
    __syncthreads();
    if (threadIdx.x == 0) g_is64 = (s_any == 0) ? 1 : 0;
}

// Convert indices to int32 and count in-degree on col.
__global__ void k_convert(const void* ei) {
    int e = blockIdx.x * blockDim.x + threadIdx.x;
    if (e >= E_EDGES) return;
    int r, c;
    if (g_is64) {
        const long long* p = (const long long*)ei;
        r = (int)p[e];
        c = (int)p[E_EDGES + e];
    } else {
        const int* p = (const int*)ei;
        r = p[e];
        c = p[E_EDGES + e];
    }
    g_row[e] = r;
    g_col[e] = c;
    atomicAdd(&g_deg[c], 1.0f);
}

__global__ void k_dinv() {
    int v = blockIdx.x * blockDim.x + threadIdx.x;
    if (v < N_NODES) g_dinv[v] = rsqrtf(g_deg[v] + 1.0f);
}

// Layer-1 scatter: t[c] += dinv[r] * x[r]   (2-dim, pre-W1 thanks to linearity)
__global__ void k_scatter1(const float* __restrict__ x) {
    int e = blockIdx.x * blockDim.x + threadIdx.x;
    if (e >= E_EDGES) return;
    int r = g_row[e], c = g_col[e];
    float dr = g_dinv[r];
    float2 xr = ((const float2*)x)[r];
    atomicAdd(&g_t[2 * c],     dr * xr.x);
    atomicAdd(&g_t[2 * c + 1], dr * xr.y);
}

// Per node: pre1 = dinv*t + dinv^2*x  (2-dim)
//           h1   = relu(pre1 @ W1 + b1)          [64]
//           s2   = dinv * (h1 @ W2)              [32]
// One warp per node; W1/b1/W2 staged in shared.
__global__ void k_node1(const float* __restrict__ x,
                        const float* __restrict__ W1,
                        const float* __restrict__ b1,
                        const float* __restrict__ W2) {
    __shared__ float sW1[128], sb1[64], sW2[2048], sh[8][64];
    for (int i = threadIdx.x; i < 128;  i += 256) sW1[i] = W1[i];
    for (int i = threadIdx.x; i < 64;   i += 256) sb1[i] = b1[i];
    for (int i = threadIdx.x; i < 2048; i += 256) sW2[i] = W2[i];
    __syncthreads();

    int warp = threadIdx.x >> 5;
    int lane = threadIdx.x & 31;
    int v = blockIdx.x * 8 + warp;
    if (v >= N_NODES) return;

    float dinv = g_dinv[v];
    float2 xv = ((const float2*)x)[v];
    float p0 = dinv * g_t[2 * v]     + dinv * dinv * xv.x;
    float p1 = dinv * g_t[2 * v + 1] + dinv * dinv * xv.y;

    float ha = fmaxf(fmaf(p0, sW1[lane],      fmaf(p1, sW1[64 + lane],      sb1[lane])),      0.0f);
    float hb = fmaxf(fmaf(p0, sW1[lane + 32], fmaf(p1, sW1[64 + lane + 32], sb1[lane + 32])), 0.0f);
    sh[warp][lane]      = ha;
    sh[warp][lane + 32] = hb;
    __syncwarp();

    float acc = 0.0f;
#pragma unroll 16
    for (int j = 0; j < 64; j++)
        acc = fmaf(sh[warp][j], sW2[j * 32 + lane], acc);
    g_s2[v * 32 + lane] = dinv * acc;
}

// Layer-2 scatter: agg2[c][0:32] += s2[r][0:32]. One warp per edge.
__global__ void k_scatter2() {
    int t = blockIdx.x * blockDim.x + threadIdx.x;
    int e = t >> 5;
    int lane = t & 31;
    if (e >= E_EDGES) return;
    int r = g_row[e], c = g_col[e];
    atomicAdd(&g_agg2[c * 32 + lane], g_s2[r * 32 + lane]);
}

// Per node: h2 = relu(dinv*(agg2 + s2) + b2)    [32]
//           a  = h2 @ Wm1[0:32]   [16]
//           c2 = h2 @ Wm1[32:64]  [16]
// One warp per node; lanes 0-15 -> a, lanes 16-31 -> c2, via shuffles.
__global__ void k_node2(const float* __restrict__ b2,
                        const float* __restrict__ Wm1) {
    __shared__ float sWm1[1056], sb2[32];
    for (int i = threadIdx.x; i < 1056; i += 256) sWm1[i] = Wm1[i];
    if (threadIdx.x < 32) sb2[threadIdx.x] = b2[threadIdx.x];
    __syncthreads();

    int t = blockIdx.x * blockDim.x + threadIdx.x;
    int v = t >> 5;
    int lane = t & 31;
    if (v >= N_NODES) return;

    float dinv = g_dinv[v];
    float h2 = fmaxf(dinv * (g_agg2[v * 32 + lane] + g_s2[v * 32 + lane]) + sb2[lane], 0.0f);

    int k = lane & 15;
    int base = (lane < 16) ? 0 : 32;
    float acc = 0.0f;
#pragma unroll
    for (int j = 0; j < 32; j++) {
        float hj = __shfl_sync(0xffffffffu, h2, j);
        acc = fmaf(hj, sWm1[(base + j) * 16 + k], acc);
    }
    if (lane < 16) g_a[v * 16 + k] = acc;
    else           g_c[v * 16 + k] = acc;
}

// Per edge: hm[k] = relu(a[r][k] + c[cl][k] + ea0*Wm1[64][k] + ea1*Wm1[65][k] + bm1[k])
//           out[e] = sum_k hm[k]*Wm2[k] + bm2
// 16 lanes per edge (2 edges/warp), 16-wide butterfly reduce.
__global__ void k_edge(const float* __restrict__ ea,
                       const float* __restrict__ Wm1,
                       const float* __restrict__ bm1,
                       const float* __restrict__ Wm2,
                       const float* __restrict__ bm2,
                       float* __restrict__ out) {
    __shared__ float sW64[16], sW65[16], sbm1[16], sWm2[16], sbm2;
    if (threadIdx.x < 16) {
        sW64[threadIdx.x] = Wm1[64 * 16 + threadIdx.x];
        sW65[threadIdx.x] = Wm1[65 * 16 + threadIdx.x];
        sbm1[threadIdx.x] = bm1[threadIdx.x];
        sWm2[threadIdx.x] = Wm2[threadIdx.x];
    }
    if (threadIdx.x == 0) sbm2 = bm2[0];
    __syncthreads();

    int t = blockIdx.x * blockDim.x + threadIdx.x;
    int e = t >> 4;
    int k = t & 15;
    if (e >= E_EDGES) return;

    int r = g_row[e], cl = g_col[e];
    float2 eav = ((const float2*)ea)[e];

    float hm = g_a[r * 16 + k] + g_c[cl * 16 + k];
    hm = fmaf(eav.x, sW64[k], hm);
    hm = fmaf(eav.y, sW65[k], hm);
    hm = fmaxf(hm + sbm1[k], 0.0f);

    float p = hm * sWm2[k];
    p += __shfl_xor_sync(0xffffffffu, p, 8, 16);
    p += __shfl_xor_sync(0xffffffffu, p, 4, 16);
    p += __shfl_xor_sync(0xffffffffu, p, 2, 16);
    p += __shfl_xor_sync(0xffffffffu, p, 1, 16);
    if (k == 0) out[e] = p + sbm2;
}

// ---------------- launch ------------------------------------------------------

extern "C" void kernel_launch(void* const* d_in, const int* in_sizes, int n_in,
                              void* d_out, int out_size) {
    const float* x   = (const float*)d_in[0];
    const void*  ei  = d_in[1];
    const float* ea  = (const float*)d_in[2];
    const float* W1  = (const float*)d_in[3];
    const float* b1  = (const float*)d_in[4];
    const float* W2  = (const float*)d_in[5];
    const float* b2  = (const float*)d_in[6];
    const float* Wm1 = (const float*)d_in[7];
    const float* bm1 = (const float*)d_in[8];
    const float* Wm2 = (const float*)d_in[9];
    const float* bm2 = (const float*)d_in[10];
    float* out = (float*)d_out;

    k_zero<<<(N_NODES * 32 + 255) / 256, 256>>>();
    k_detect<<<1, 256>>>((const int*)ei);
    k_convert<<<(E_EDGES + 255) / 256, 256>>>(ei);
    k_dinv<<<(N_NODES + 255) / 256, 256>>>();
    k_scatter1<<<(E_EDGES + 255) / 256, 256>>>(x);
    k_node1<<<(N_NODES + 7) / 8, 256>>>(x, W1, b1, W2);
    {
        long long threads = (long long)E_EDGES * 32;
        k_scatter2<<<(unsigned)((threads + 255) / 256), 256>>>();
    }
    {
        long long threads = (long long)N_NODES * 32;
        k_node2<<<(unsigned)((threads + 255) / 256), 256>>>(b2, Wm1);
    }
    {
        long long threads = (long long)E_EDGES * 16;
        k_edge<<<(unsigned)((threads + 255) / 256), 256>>>(ea, Wm1, bm1, Wm2, bm2, out);
    }
}

// round 2
// speedup vs baseline: 1.3216x; 1.3216x over previous
#include <cuda_runtime.h>

#define N_NODES 100000
#define E_EDGES 1600000
#define NB_SCAN 98   // ceil(100000/1024)

// ---------------- scratch (device globals; no allocations allowed) ----------
__device__ int   g_is64;
__device__ int   g_row[E_EDGES];
__device__ int   g_col[E_EDGES];
__device__ int   g_degi[N_NODES];        // in-degree (edges only)
__device__ int   g_scan[N_NODES];        // per-block inclusive scan of deg
__device__ int   g_part[NB_SCAN];        // block partial sums -> exclusive-scanned
__device__ int   g_start[N_NODES];       // CSR offsets (exclusive)
__device__ int   g_cur[N_NODES];         // fill cursors
__device__ int   g_csr[E_EDGES];         // source node per in-edge, grouped by target
__device__ float g_dinv[N_NODES];
__device__ float g_s2[N_NODES * 32];     // dinv[v] * (h1[v] @ W2)
__device__ float g_a[N_NODES * 16];      // h2[v] @ Wm1[0:32]
__device__ float g_c[N_NODES * 16];      // h2[v] @ Wm1[32:64]

// ---------------- kernels ----------------------------------------------------

__global__ void k_zero() {
    int i = blockIdx.x * blockDim.x + threadIdx.x;
    if (i < N_NODES) g_degi[i] = 0;
}

// Detect int64 vs int32 edge_index (JAX may emit either).
__global__ void k_detect(const int* ei32) {
    __shared__ int s_any;
    if (threadIdx.x == 0) s_any = 0;
    __syncthreads();
    int v = 0;
    for (int i = threadIdx.x; i < 1024; i += blockDim.x)
        v |= ei32[2 * i + 1];
    if (v) atomicOr(&s_any, 1);
    __syncthreads();
    if (threadIdx.x == 0) g_is64 = (s_any == 0) ? 1 : 0;
}

// Convert indices to int32 and count in-degree on col.
__global__ void k_convert(const void* ei) {
    int e = blockIdx.x * blockDim.x + threadIdx.x;
    if (e >= E_EDGES) return;
    int r, c;
    if (g_is64) {
        const long long* p = (const long long*)ei;
        r = (int)p[e];
        c = (int)p[E_EDGES + e];
    } else {
        const int* p = (const int*)ei;
        r = p[e];
        c = p[E_EDGES + e];
    }
    g_row[e] = r;
    g_col[e] = c;
    atomicAdd(&g_degi[c], 1);
}

// --- 3-kernel exclusive scan of g_degi -> g_start ---
__global__ void k_scan1() {
    __shared__ int s[1024];
    int i = blockIdx.x * 1024 + threadIdx.x;
    int v = (i < N_NODES) ? g_degi[i] : 0;
    s[threadIdx.x] = v;
    __syncthreads();
#pragma unroll
    for (int d = 1; d < 1024; d <<= 1) {
        int t = (threadIdx.x >= d) ? s[threadIdx.x - d] : 0;
        __syncthreads();
        s[threadIdx.x] += t;
        __syncthreads();
    }
    if (i < N_NODES) g_scan[i] = s[threadIdx.x];          // inclusive within block
    if (threadIdx.x == 1023) g_part[blockIdx.x] = s[1023];
}

__global__ void k_scan2() {
    if (threadIdx.x == 0) {
        int acc = 0;
        for (int b = 0; b < NB_SCAN; b++) { int t = g_part[b]; g_part[b] = acc; acc += t; }
    }
}

__global__ void k_scan3() {
    int v = blockIdx.x * blockDim.x + threadIdx.x;
    if (v >= N_NODES) return;
    int deg = g_degi[v];
    int st = g_scan[v] - deg + g_part[v >> 10];
    g_start[v] = st;
    g_cur[v]   = st;
    g_dinv[v]  = rsqrtf((float)deg + 1.0f);
}

// Scatter edges into CSR (grouped by target node).
__global__ void k_fill() {
    int e = blockIdx.x * blockDim.x + threadIdx.x;
    if (e >= E_EDGES) return;
    int c = g_col[e];
    int idx = atomicAdd(&g_cur[c], 1);
    g_csr[idx] = g_row[e];
}

// Per node (warp): aggregate t = sum dinv[r]*x[r] over in-edges,
//   pre1 = dinv*t + dinv^2*x ; h1 = relu(pre1@W1+b1) [64] ; s2 = dinv*(h1@W2) [32]
__global__ void k_node1(const float* __restrict__ x,
                        const float* __restrict__ W1,
                        const float* __restrict__ b1,
                        const float* __restrict__ W2) {
    __shared__ float sW1[128], sb1[64], sW2[2048], sh[8][64];
    for (int i = threadIdx.x; i < 128;  i += 256) sW1[i] = W1[i];
    for (int i = threadIdx.x; i < 64;   i += 256) sb1[i] = b1[i];
    for (int i = threadIdx.x; i < 2048; i += 256) sW2[i] = W2[i];
    __syncthreads();

    int warp = threadIdx.x >> 5;
    int lane = threadIdx.x & 31;
    int v = blockIdx.x * 8 + warp;
    if (v >= N_NODES) return;

    int start = g_start[v];
    int deg   = g_degi[v];
    float a0 = 0.0f, a1 = 0.0f;
    for (int i = lane; i < deg; i += 32) {
        int r = g_csr[start + i];
        float dr = g_dinv[r];
        float2 xr = ((const float2*)x)[r];
        a0 = fmaf(dr, xr.x, a0);
        a1 = fmaf(dr, xr.y, a1);
    }
#pragma unroll
    for (int o = 16; o; o >>= 1) {
        a0 += __shfl_xor_sync(0xffffffffu, a0, o);
        a1 += __shfl_xor_sync(0xffffffffu, a1, o);
    }

    float dinv = g_dinv[v];
    float2 xv = ((const float2*)x)[v];
    float p0 = dinv * a0 + dinv * dinv * xv.x;
    float p1 = dinv * a1 + dinv * dinv * xv.y;

    float ha = fmaxf(fmaf(p0, sW1[lane],      fmaf(p1, sW1[64 + lane],      sb1[lane])),      0.0f);
    float hb = fmaxf(fmaf(p0, sW1[lane + 32], fmaf(p1, sW1[64 + lane + 32], sb1[lane + 32])), 0.0f);
    sh[warp][lane]      = ha;
    sh[warp][lane + 32] = hb;
    __syncwarp();

    float acc = 0.0f;
#pragma unroll 16
    for (int j = 0; j < 64; j++)
        acc = fmaf(sh[warp][j], sW2[j * 32 + lane], acc);
    g_s2[v * 32 + lane] = dinv * acc;
}

// Per node (warp): aggregate 32-dim s2 rows over in-edges (pure gathers),
//   h2 = relu(dinv*(agg + s2[v]) + b2) [32]
//   a  = h2 @ Wm1[0:32] [16] ; c = h2 @ Wm1[32:64] [16]
__global__ void k_node2(const float* __restrict__ b2,
                        const float* __restrict__ Wm1) {
    __shared__ float sWm1[1056], sb2[32];
    for (int i = threadIdx.x; i < 1056; i += 256) sWm1[i] = Wm1[i];
    if (threadIdx.x < 32) sb2[threadIdx.x] = b2[threadIdx.x];
    __syncthreads();

    int warp = threadIdx.x >> 5;
    int lane = threadIdx.x & 31;
    int v = blockIdx.x * 8 + warp;
    if (v >= N_NODES) return;

    int start = g_start[v];
    int deg   = g_degi[v];
    float acc = 0.0f;
    for (int base = 0; base < deg; base += 32) {
        int rem = deg - base;
        int idx = (lane < rem) ? g_csr[start + base + lane] : 0;
        int m = rem < 32 ? rem : 32;
        for (int j = 0; j < m; j++) {
            int r = __shfl_sync(0xffffffffu, idx, j);
            acc += g_s2[r * 32 + lane];
        }
    }

    float dinv = g_dinv[v];
    float h2 = fmaxf(fmaf(dinv, acc + g_s2[v * 32 + lane], sb2[lane]), 0.0f);

    int k = lane & 15;
    int rowbase = (lane < 16) ? 0 : 32;
    float r2 = 0.0f;
#pragma unroll
    for (int j = 0; j < 32; j++) {
        float hj = __shfl_sync(0xffffffffu, h2, j);
        r2 = fmaf(hj, sWm1[(rowbase + j) * 16 + k], r2);
    }
    if (lane < 16) g_a[v * 16 + k] = r2;
    else           g_c[v * 16 + k] = r2;
}

// Per edge (16 lanes): hm = relu(a[r]+c[cl]+ea@Wm1[64:66]+bm1), out = hm@Wm2+bm2
__global__ void k_edge(const float* __restrict__ ea,
                       const float* __restrict__ Wm1,
                       const float* __restrict__ bm1,
                       const float* __restrict__ Wm2,
                       const float* __restrict__ bm2,
                       float* __restrict__ out) {
    __shared__ float sW64[16], sW65[16], sbm1[16], sWm2[16], sbm2;
    if (threadIdx.x < 16) {
        sW64[threadIdx.x] = Wm1[64 * 16 + threadIdx.x];
        sW65[threadIdx.x] = Wm1[65 * 16 + threadIdx.x];
        sbm1[threadIdx.x] = bm1[threadIdx.x];
        sWm2[threadIdx.x] = Wm2[threadIdx.x];
    }
    if (threadIdx.x == 0) sbm2 = bm2[0];
    __syncthreads();

    int t = blockIdx.x * blockDim.x + threadIdx.x;
    int e = t >> 4;
    int k = t & 15;
    if (e >= E_EDGES) return;

    int r = g_row[e], cl = g_col[e];
    float2 eav = ((const float2*)ea)[e];

    float hm = g_a[r * 16 + k] + g_c[cl * 16 + k];
    hm = fmaf(eav.x, sW64[k], hm);
    hm = fmaf(eav.y, sW65[k], hm);
    hm = fmaxf(hm + sbm1[k], 0.0f);

    float p = hm * sWm2[k];
    p += __shfl_xor_sync(0xffffffffu, p, 8, 16);
    p += __shfl_xor_sync(0xffffffffu, p, 4, 16);
    p += __shfl_xor_sync(0xffffffffu, p, 2, 16);
    p += __shfl_xor_sync(0xffffffffu, p, 1, 16);
    if (k == 0) out[e] = p + sbm2;
}

// ---------------- launch ------------------------------------------------------

extern "C" void kernel_launch(void* const* d_in, const int* in_sizes, int n_in,
                              void* d_out, int out_size) {
    const float* x   = (const float*)d_in[0];
    const void*  ei  = d_in[1];
    const float* ea  = (const float*)d_in[2];
    const float* W1  = (const float*)d_in[3];
    const float* b1  = (const float*)d_in[4];
    const float* W2  = (const float*)d_in[5];
    const float* b2  = (const float*)d_in[6];
    const float* Wm1 = (const float*)d_in[7];
    const float* bm1 = (const float*)d_in[8];
    const float* Wm2 = (const float*)d_in[9];
    const float* bm2 = (const float*)d_in[10];
    float* out = (float*)d_out;

    k_zero<<<(N_NODES + 255) / 256, 256>>>();
    k_detect<<<1, 256>>>((const int*)ei);
    k_convert<<<(E_EDGES + 255) / 256, 256>>>(ei);
    k_scan1<<<NB_SCAN, 1024>>>();
    k_scan2<<<1, 32>>>();
    k_scan3<<<(N_NODES + 255) / 256, 256>>>();
    k_fill<<<(E_EDGES + 255) / 256, 256>>>();
    k_node1<<<(N_NODES + 7) / 8, 256>>>(x, W1, b1, W2);
    k_node2<<<(N_NODES + 7) / 8, 256>>>(b2, Wm1);
    {
        long long threads = (long long)E_EDGES * 16;
        k_edge<<<(unsigned)((threads + 255) / 256), 256>>>(ea, Wm1, bm1, Wm2, bm2, out);
    }
}

// round 3
// speedup vs baseline: 1.5942x; 1.2062x over previous
#include <cuda_runtime.h>

#define N_NODES 100000
#define E_EDGES 1600000
#define NB_SCAN 98   // ceil(100000/1024)

// ---------------- scratch (device globals; no allocations allowed) ----------
__device__ int   g_is64;
__device__ int   g_row[E_EDGES];
__device__ int   g_col[E_EDGES];
__device__ int   g_degi[N_NODES];        // in-degree (edges only)
__device__ int   g_scan[N_NODES];        // per-block inclusive scan of deg
__device__ int   g_part[NB_SCAN];        // block partial sums -> exclusive-scanned
__device__ int   g_start[N_NODES];       // CSR offsets (exclusive)
__device__ int   g_cur[N_NODES];         // fill cursors
__device__ int   g_csr[E_EDGES];         // source node per in-edge, grouped by target
__device__ float g_dinv[N_NODES];
__device__ float g_s2[N_NODES * 32];     // dinv[v] * (h1[v] @ W2)
__device__ float g_a[N_NODES * 16];      // h2[v] @ Wm1[0:32]
__device__ float g_c[N_NODES * 16];      // h2[v] @ Wm1[32:64]

// ---------------- kernels ----------------------------------------------------

// Block 0: detect int64 vs int32 edge_index. Other blocks: zero g_degi.
__global__ void k_zero_detect(const int* ei32) {
    if (blockIdx.x == 0) {
        __shared__ int s_any;
        if (threadIdx.x == 0) s_any = 0;
        __syncthreads();
        int v = 0;
        for (int i = threadIdx.x; i < 1024; i += blockDim.x)
            v |= ei32[2 * i + 1];
        if (v) atomicOr(&s_any, 1);
        __syncthreads();
        if (threadIdx.x == 0) g_is64 = (s_any == 0) ? 1 : 0;
    } else {
        int i = (blockIdx.x - 1) * 256 + threadIdx.x;
        if (i < N_NODES) g_degi[i] = 0;
    }
}

// Convert indices to int32 and count in-degree on col.
__global__ void k_convert(const void* ei) {
    int e = blockIdx.x * blockDim.x + threadIdx.x;
    if (e >= E_EDGES) return;
    int r, c;
    if (g_is64) {
        const long long* p = (const long long*)ei;
        r = (int)p[e];
        c = (int)p[E_EDGES + e];
    } else {
        const int* p = (const int*)ei;
        r = p[e];
        c = p[E_EDGES + e];
    }
    g_row[e] = r;
    g_col[e] = c;
    atomicAdd(&g_degi[c], 1);
}

// --- 3-kernel exclusive scan of g_degi -> g_start ---
__global__ void k_scan1() {
    __shared__ int s[1024];
    int i = blockIdx.x * 1024 + threadIdx.x;
    int v = (i < N_NODES) ? g_degi[i] : 0;
    s[threadIdx.x] = v;
    __syncthreads();
#pragma unroll
    for (int d = 1; d < 1024; d <<= 1) {
        int t = (threadIdx.x >= d) ? s[threadIdx.x - d] : 0;
        __syncthreads();
        s[threadIdx.x] += t;
        __syncthreads();
    }
    if (i < N_NODES) g_scan[i] = s[threadIdx.x];          // inclusive within block
    if (threadIdx.x == 1023) g_part[blockIdx.x] = s[1023];
}

__global__ void k_scan2() {
    if (threadIdx.x == 0) {
        int acc = 0;
        for (int b = 0; b < NB_SCAN; b++) { int t = g_part[b]; g_part[b] = acc; acc += t; }
    }
}

__global__ void k_scan3() {
    int v = blockIdx.x * blockDim.x + threadIdx.x;
    if (v >= N_NODES) return;
    int deg = g_degi[v];
    int st = g_scan[v] - deg + g_part[v >> 10];
    g_start[v] = st;
    g_cur[v]   = st;
    g_dinv[v]  = rsqrtf((float)deg + 1.0f);
}

// Scatter edges into CSR (grouped by target node).
__global__ void k_fill() {
    int e = blockIdx.x * blockDim.x + threadIdx.x;
    if (e >= E_EDGES) return;
    int c = g_col[e];
    int idx = atomicAdd(&g_cur[c], 1);
    g_csr[idx] = g_row[e];
}

// Per node (warp): aggregate t = sum dinv[r]*x[r] over in-edges,
//   pre1 = dinv*t + dinv^2*x ; h1 = relu(pre1@W1+b1) [64] ; s2 = dinv*(h1@W2) [32]
__global__ void k_node1(const float* __restrict__ x,
                        const float* __restrict__ W1,
                        const float* __restrict__ b1,
                        const float* __restrict__ W2) {
    __shared__ float sW1[128], sb1[64], sW2[2048], sh[8][64];
    for (int i = threadIdx.x; i < 128;  i += 256) sW1[i] = W1[i];
    for (int i = threadIdx.x; i < 64;   i += 256) sb1[i] = b1[i];
    for (int i = threadIdx.x; i < 2048; i += 256) sW2[i] = W2[i];
    __syncthreads();

    int warp = threadIdx.x >> 5;
    int lane = threadIdx.x & 31;
    int v = blockIdx.x * 8 + warp;
    if (v >= N_NODES) return;

    int start = g_start[v];
    int deg   = g_degi[v];
    float a0 = 0.0f, a1 = 0.0f;
    for (int i = lane; i < deg; i += 32) {
        int r = g_csr[start + i];
        float dr = g_dinv[r];
        float2 xr = ((const float2*)x)[r];
        a0 = fmaf(dr, xr.x, a0);
        a1 = fmaf(dr, xr.y, a1);
    }
#pragma unroll
    for (int o = 16; o; o >>= 1) {
        a0 += __shfl_xor_sync(0xffffffffu, a0, o);
        a1 += __shfl_xor_sync(0xffffffffu, a1, o);
    }

    float dinv = g_dinv[v];
    float2 xv = ((const float2*)x)[v];
    float p0 = dinv * a0 + dinv * dinv * xv.x;
    float p1 = dinv * a1 + dinv * dinv * xv.y;

    float ha = fmaxf(fmaf(p0, sW1[lane],      fmaf(p1, sW1[64 + lane],      sb1[lane])),      0.0f);
    float hb = fmaxf(fmaf(p0, sW1[lane + 32], fmaf(p1, sW1[64 + lane + 32], sb1[lane + 32])), 0.0f);
    sh[warp][lane]      = ha;
    sh[warp][lane + 32] = hb;
    __syncwarp();

    float acc = 0.0f;
#pragma unroll 16
    for (int j = 0; j < 64; j++)
        acc = fmaf(sh[warp][j], sW2[j * 32 + lane], acc);
    g_s2[v * 32 + lane] = dinv * acc;
}

// Per node (warp, 4 rows in flight): warp splits into 4 subgroups of 8 lanes.
// Subgroup `sub` walks edges sub, sub+4, ...; lane q within subgroup holds
// dims 4q..4q+3 of the 32-dim s2 row via one float4 load. Cross-subgroup
// xor-shuffle reduce, then h2 = relu(dinv*(agg+s2[v])+b2) and the two 32x16
// Wm1 half-products from shared.
__global__ void k_node2(const float* __restrict__ b2,
                        const float* __restrict__ Wm1) {
    __shared__ float sWm1[1056], sb2[32], sh[8][32];
    for (int i = threadIdx.x; i < 1056; i += 256) sWm1[i] = Wm1[i];
    if (threadIdx.x < 32) sb2[threadIdx.x] = b2[threadIdx.x];
    __syncthreads();

    int warp = threadIdx.x >> 5;
    int lane = threadIdx.x & 31;
    int v = blockIdx.x * 8 + warp;
    if (v >= N_NODES) return;

    int sub = lane >> 3;        // 0..3
    int q   = lane & 7;         // 0..7  -> dims 4q..4q+3
    int start = g_start[v];
    int deg   = g_degi[v];

    float4 acc = make_float4(0.0f, 0.0f, 0.0f, 0.0f);
    for (int i = sub; i < deg; i += 4) {
        int r = g_csr[start + i];
        float4 sv = ((const float4*)g_s2)[r * 8 + q];
        acc.x += sv.x; acc.y += sv.y; acc.z += sv.z; acc.w += sv.w;
    }
#pragma unroll
    for (int o = 8; o <= 16; o <<= 1) {
        acc.x += __shfl_xor_sync(0xffffffffu, acc.x, o);
        acc.y += __shfl_xor_sync(0xffffffffu, acc.y, o);
        acc.z += __shfl_xor_sync(0xffffffffu, acc.z, o);
        acc.w += __shfl_xor_sync(0xffffffffu, acc.w, o);
    }

    float dinv = g_dinv[v];
    float4 own = ((const float4*)g_s2)[v * 8 + q];
    float h0 = fmaxf(fmaf(dinv, acc.x + own.x, sb2[4 * q]),     0.0f);
    float h1 = fmaxf(fmaf(dinv, acc.y + own.y, sb2[4 * q + 1]), 0.0f);
    float h2 = fmaxf(fmaf(dinv, acc.z + own.z, sb2[4 * q + 2]), 0.0f);
    float h3 = fmaxf(fmaf(dinv, acc.w + own.w, sb2[4 * q + 3]), 0.0f);
    if (sub == 0) {
        sh[warp][4 * q]     = h0;
        sh[warp][4 * q + 1] = h1;
        sh[warp][4 * q + 2] = h2;
        sh[warp][4 * q + 3] = h3;
    }
    __syncwarp();

    int k = lane & 15;
    int rowbase = (lane < 16) ? 0 : 32;
    float r2 = 0.0f;
#pragma unroll
    for (int j = 0; j < 32; j++)
        r2 = fmaf(sh[warp][j], sWm1[(rowbase + j) * 16 + k], r2);
    if (lane < 16) g_a[v * 16 + k] = r2;
    else           g_c[v * 16 + k] = r2;
}

// Per edge (8 lanes, 2 dims/lane): hm = relu(a[r]+c[cl]+ea@Wm1[64:66]+bm1),
// out = hm@Wm2+bm2 via 8-wide butterfly reduce.
__global__ void k_edge(const float* __restrict__ ea,
                       const float* __restrict__ Wm1,
                       const float* __restrict__ bm1,
                       const float* __restrict__ Wm2,
                       const float* __restrict__ bm2,
                       float* __restrict__ out) {
    __shared__ float sW64[16], sW65[16], sbm1[16], sWm2[16], sbm2;
    if (threadIdx.x < 16) {
        sW64[threadIdx.x] = Wm1[64 * 16 + threadIdx.x];
        sW65[threadIdx.x] = Wm1[65 * 16 + threadIdx.x];
        sbm1[threadIdx.x] = bm1[threadIdx.x];
        sWm2[threadIdx.x] = Wm2[threadIdx.x];
    }
    if (threadIdx.x == 0) sbm2 = bm2[0];
    __syncthreads();

    int t = blockIdx.x * blockDim.x + threadIdx.x;
    int e = t >> 3;
    int g = t & 7;              // dims 2g, 2g+1
    if (e >= E_EDGES) return;

    int r = g_row[e], cl = g_col[e];
    float2 eav = ((const float2*)ea)[e];
    float2 av = ((const float2*)g_a)[r * 8 + g];
    float2 cv = ((const float2*)g_c)[cl * 8 + g];

    int k0 = 2 * g, k1 = 2 * g + 1;
    float hm0 = av.x + cv.x;
    hm0 = fmaf(eav.x, sW64[k0], hm0);
    hm0 = fmaf(eav.y, sW65[k0], hm0);
    hm0 = fmaxf(hm0 + sbm1[k0], 0.0f);
    float hm1 = av.y + cv.y;
    hm1 = fmaf(eav.x, sW64[k1], hm1);
    hm1 = fmaf(eav.y, sW65[k1], hm1);
    hm1 = fmaxf(hm1 + sbm1[k1], 0.0f);

    float p = fmaf(hm0, sWm2[k0], hm1 * sWm2[k1]);
    p += __shfl_xor_sync(0xffffffffu, p, 4, 8);
    p += __shfl_xor_sync(0xffffffffu, p, 2, 8);
    p += __shfl_xor_sync(0xffffffffu, p, 1, 8);
    if (g == 0) out[e] = p + sbm2;
}

// ---------------- launch ------------------------------------------------------

extern "C" void kernel_launch(void* const* d_in, const int* in_sizes, int n_in,
                              void* d_out, int out_size) {
    const float* x   = (const float*)d_in[0];
    const void*  ei  = d_in[1];
    const float* ea  = (const float*)d_in[2];
    const float* W1  = (const float*)d_in[3];
    const float* b1  = (const float*)d_in[4];
    const float* W2  = (const float*)d_in[5];
    const float* b2  = (const float*)d_in[6];
    const float* Wm1 = (const float*)d_in[7];
    const float* bm1 = (const float*)d_in[8];
    const float* Wm2 = (const float*)d_in[9];
    const float* bm2 = (const float*)d_in[10];
    float* out = (float*)d_out;

    k_zero_detect<<<(N_NODES + 255) / 256 + 1, 256>>>((const int*)ei);
    k_convert<<<(E_EDGES + 255) / 256, 256>>>(ei);
    k_scan1<<<NB_SCAN, 1024>>>();
    k_scan2<<<1, 32>>>();
    k_scan3<<<(N_NODES + 255) / 256, 256>>>();
    k_fill<<<(E_EDGES + 255) / 256, 256>>>();
    k_node1<<<(N_NODES + 7) / 8, 256>>>(x, W1, b1, W2);
    k_node2<<<(N_NODES + 7) / 8, 256>>>(b2, Wm1);
    {
        long long threads = (long long)E_EDGES * 8;
        k_edge<<<(unsigned)((threads + 255) / 256), 256>>>(ea, Wm1, bm1, Wm2, bm2, out);
    }
}